// round 2
// baseline (speedup 1.0000x reference)
#include <cuda_runtime.h>

// DistMult scoring:
//   pos[e]          = sum_d A[h_e,d] * K[d] * B[t_e,d]
//   head[e*4+j]     = sum_d A[hb[e,j],d] * K[d] * B[t_e,d]
//   tail[e*4+j]     = sum_d A[h_e,d] * K[d] * B[tb[e,j],d]
// out = [pos (E), head (4E), tail (4E)]
//
// One warp per edge. Each lane owns 4 contiguous dims (float4), D=128.
// ak = a_h * k and bk = b_t * k are computed once; 9 dot products reduced
// via warp shuffles.

#define D 128
#define NEG 4

__device__ __forceinline__ float warp_reduce(float v) {
    v += __shfl_xor_sync(0xFFFFFFFF, v, 16);
    v += __shfl_xor_sync(0xFFFFFFFF, v, 8);
    v += __shfl_xor_sync(0xFFFFFFFF, v, 4);
    v += __shfl_xor_sync(0xFFFFFFFF, v, 2);
    v += __shfl_xor_sync(0xFFFFFFFF, v, 1);
    return v;
}

__device__ __forceinline__ float dot4(float4 a, float4 b) {
    return a.x * b.x + a.y * b.y + a.z * b.z + a.w * b.w;
}

__global__ void __launch_bounds__(256) distmult_kernel(
    const float* __restrict__ A,     // [N_A, 128]
    const float* __restrict__ B,     // [N_B, 128]
    const float* __restrict__ K,     // [128]
    const int*   __restrict__ ep,    // [2, E]
    const int*   __restrict__ hb,    // [E, 4]
    const int*   __restrict__ tb,    // [E, 4]
    float*       __restrict__ out,   // [9E]
    int E)
{
    int warp = (int)((blockIdx.x * (unsigned)blockDim.x + threadIdx.x) >> 5);
    int lane = threadIdx.x & 31;
    if (warp >= E) return;

    // indices (broadcast loads, L1/L2-hit)
    int h = __ldg(&ep[warp]);
    int t = __ldg(&ep[E + warp]);
    int4 hbi = __ldg((const int4*)(hb) + warp);
    int4 tbi = __ldg((const int4*)(tb) + warp);
    int hidx[NEG] = {hbi.x, hbi.y, hbi.z, hbi.w};
    int tidx[NEG] = {tbi.x, tbi.y, tbi.z, tbi.w};

    const float4* A4 = (const float4*)A;
    const float4* B4 = (const float4*)B;

    float4 k4 = __ldg((const float4*)K + lane);
    float4 a  = __ldg(A4 + (size_t)h * (D / 4) + lane);
    float4 b  = __ldg(B4 + (size_t)t * (D / 4) + lane);

    float4 ak = make_float4(a.x * k4.x, a.y * k4.y, a.z * k4.z, a.w * k4.w);
    float4 bk = make_float4(b.x * k4.x, b.y * k4.y, b.z * k4.z, b.w * k4.w);

    // issue all 8 corrupt-row loads up front for MLP
    float4 ha[NEG], tbv[NEG];
#pragma unroll
    for (int j = 0; j < NEG; j++) {
        ha[j]  = __ldg(A4 + (size_t)hidx[j] * (D / 4) + lane);
        tbv[j] = __ldg(B4 + (size_t)tidx[j] * (D / 4) + lane);
    }

    float pos = dot4(ak, b);   // == dot(a, bk)
    float hs[NEG], ts[NEG];
#pragma unroll
    for (int j = 0; j < NEG; j++) {
        hs[j] = dot4(ha[j], bk);
        ts[j] = dot4(ak, tbv[j]);
    }

    pos = warp_reduce(pos);
#pragma unroll
    for (int j = 0; j < NEG; j++) {
        hs[j] = warp_reduce(hs[j]);
        ts[j] = warp_reduce(ts[j]);
    }

    if (lane == 0) {
        out[warp] = pos;
        size_t hbase = (size_t)E + (size_t)warp * NEG;
        size_t tbase = (size_t)E * (1 + NEG) + (size_t)warp * NEG;
#pragma unroll
        for (int j = 0; j < NEG; j++) {
            out[hbase + j] = hs[j];
            out[tbase + j] = ts[j];
        }
    }
}

extern "C" void kernel_launch(void* const* d_in, const int* in_sizes, int n_in,
                              void* d_out, int out_size) {
    const float* emb_A = (const float*)d_in[0];
    const float* emb_B = (const float*)d_in[1];
    const float* rel_k = (const float*)d_in[2];
    const int*   ep    = (const int*)d_in[3];
    const int*   hb    = (const int*)d_in[4];
    const int*   tb    = (const int*)d_in[5];
    float*       out   = (float*)d_out;

    int E = in_sizes[3] / 2;

    // 8 warps per block -> 8 edges per block
    int block = 256;
    int warps_per_block = block / 32;
    int grid = (E + warps_per_block - 1) / warps_per_block;

    distmult_kernel<<<grid, block>>>(emb_A, emb_B, rel_k, ep, hb, tb, out, E);
}

// round 3
// speedup vs baseline: 1.0330x; 1.0330x over previous
#include <cuda_runtime.h>

// DistMult scoring, warp-per-edge:
//   pos[e]      = sum_d A[h_e,d] * K[d] * B[t_e,d]
//   head[e*4+j] = sum_d A[hb[e,j],d] * K[d] * B[t_e,d]
//   tail[e*4+j] = sum_d A[h_e,d] * K[d] * B[tb[e,j],d]
// out = [pos (E), head (4E), tail (4E)]
//
// R2 changes vs R1:
//  - embedding gathers use L2::evict_last cache policy (keep the 102MB
//    embedding tables resident in L2 across graph replays)
//  - outputs staged in smem and written coalesced with st.global.cs
//    (9 scattered STG.32 wavefronts/edge -> ~5 wavefronts/block)

#define D 128
#define NEG 4
#define WPB 8  // warps (edges) per block

__device__ __forceinline__ float warp_reduce(float v) {
    v += __shfl_xor_sync(0xFFFFFFFFu, v, 16);
    v += __shfl_xor_sync(0xFFFFFFFFu, v, 8);
    v += __shfl_xor_sync(0xFFFFFFFFu, v, 4);
    v += __shfl_xor_sync(0xFFFFFFFFu, v, 2);
    v += __shfl_xor_sync(0xFFFFFFFFu, v, 1);
    return v;
}

__device__ __forceinline__ float dot4(float4 a, float4 b) {
    return a.x * b.x + a.y * b.y + a.z * b.z + a.w * b.w;
}

// 16B load, L1 non-coherent path, L2 evict_last policy
__device__ __forceinline__ float4 ldg_resident(const float4* p, unsigned long long pol) {
    float4 r;
    asm volatile(
        "ld.global.nc.L2::cache_hint.v4.f32 {%0,%1,%2,%3}, [%4], %5;"
        : "=f"(r.x), "=f"(r.y), "=f"(r.z), "=f"(r.w)
        : "l"(p), "l"(pol));
    return r;
}

__global__ void __launch_bounds__(32 * WPB) distmult_kernel(
    const float* __restrict__ A,     // [N_A, 128]
    const float* __restrict__ B,     // [N_B, 128]
    const float* __restrict__ K,     // [128]
    const int*   __restrict__ ep,    // [2, E]
    const int*   __restrict__ hb,    // [E, 4]
    const int*   __restrict__ tb,    // [E, 4]
    float*       __restrict__ out,   // [9E]
    int E)
{
    __shared__ float s[WPB][9];

    int w    = threadIdx.x >> 5;
    int lane = threadIdx.x & 31;
    int e    = blockIdx.x * WPB + w;

    unsigned long long pol;
    asm volatile("createpolicy.fractional.L2::evict_last.b64 %0, 1.0;" : "=l"(pol));

    if (e < E) {
        int h = __ldg(&ep[e]);
        int t = __ldg(&ep[E + e]);
        int4 hbi = __ldg((const int4*)(hb) + e);
        int4 tbi = __ldg((const int4*)(tb) + e);
        int hidx[NEG] = {hbi.x, hbi.y, hbi.z, hbi.w};
        int tidx[NEG] = {tbi.x, tbi.y, tbi.z, tbi.w};

        const float4* A4 = (const float4*)A;
        const float4* B4 = (const float4*)B;

        float4 k4 = __ldg((const float4*)K + lane);
        float4 a  = ldg_resident(A4 + (size_t)h * (D / 4) + lane, pol);
        float4 b  = ldg_resident(B4 + (size_t)t * (D / 4) + lane, pol);

        float4 ak = make_float4(a.x * k4.x, a.y * k4.y, a.z * k4.z, a.w * k4.w);
        float4 bk = make_float4(b.x * k4.x, b.y * k4.y, b.z * k4.z, b.w * k4.w);

        // batch all 8 corrupt-row gathers for MLP
        float4 ha[NEG], tv[NEG];
#pragma unroll
        for (int j = 0; j < NEG; j++) {
            ha[j] = ldg_resident(A4 + (size_t)hidx[j] * (D / 4) + lane, pol);
            tv[j] = ldg_resident(B4 + (size_t)tidx[j] * (D / 4) + lane, pol);
        }

        float pos = dot4(ak, b);
        float hs[NEG], ts[NEG];
#pragma unroll
        for (int j = 0; j < NEG; j++) {
            hs[j] = dot4(ha[j], bk);
            ts[j] = dot4(ak, tv[j]);
        }

        pos = warp_reduce(pos);
#pragma unroll
        for (int j = 0; j < NEG; j++) {
            hs[j] = warp_reduce(hs[j]);
            ts[j] = warp_reduce(ts[j]);
        }

        // route score j to lane j (all lanes hold all results after xor-reduce)
        float v = pos;
        if (lane == 1) v = hs[0];
        if (lane == 2) v = hs[1];
        if (lane == 3) v = hs[2];
        if (lane == 4) v = hs[3];
        if (lane == 5) v = ts[0];
        if (lane == 6) v = ts[1];
        if (lane == 7) v = ts[2];
        if (lane == 8) v = ts[3];
        if (lane < 9) s[w][lane] = v;
    }
    __syncthreads();

    // coalesced block-level stores
    int e0 = blockIdx.x * WPB;
    int nb = E - e0; if (nb > WPB) nb = WPB;
    if (nb > 0) {
        int t = threadIdx.x;
        if (t < nb)
            __stcs(&out[e0 + t], s[t][0]);
        if (t < nb * NEG) {
            int we = t >> 2, j = t & 3;
            __stcs(&out[(size_t)E + (size_t)e0 * NEG + t], s[we][1 + j]);
            __stcs(&out[(size_t)E * (1 + NEG) + (size_t)e0 * NEG + t], s[we][5 + j]);
        }
    }
}

extern "C" void kernel_launch(void* const* d_in, const int* in_sizes, int n_in,
                              void* d_out, int out_size) {
    const float* emb_A = (const float*)d_in[0];
    const float* emb_B = (const float*)d_in[1];
    const float* rel_k = (const float*)d_in[2];
    const int*   ep    = (const int*)d_in[3];
    const int*   hb    = (const int*)d_in[4];
    const int*   tb    = (const int*)d_in[5];
    float*       out   = (float*)d_out;

    int E = in_sizes[3] / 2;

    int block = 32 * WPB;
    int grid = (E + WPB - 1) / WPB;
    distmult_kernel<<<grid, block>>>(emb_A, emb_B, rel_k, ep, hb, tb, out, E);
}

// round 4
// speedup vs baseline: 1.0742x; 1.0399x over previous
#include <cuda_runtime.h>

// DistMult scoring, warp-per-edge:
//   pos[e]      = sum_d A[h_e,d] * K[d] * B[t_e,d]
//   head[e*4+j] = sum_d A[hb[e,j],d] * K[d] * B[t_e,d]
//   tail[e*4+j] = sum_d A[h_e,d] * K[d] * B[tb[e,j],d]
// out = [pos (E), head (4E), tail (4E)]
//
// R3: the 8 corrupt-row gathers go through cp.async (LDGSTS) into smem so
// they hold no registers while in flight -> full MLP=10 per warp AND lower
// register count (higher occupancy). Each lane reads back only the 16B it
// deposited, so no extra synchronization is needed after wait_group 0.

#define D 128
#define NEG 4
#define WPB 8  // warps (edges) per block

__device__ __forceinline__ float warp_reduce(float v) {
    v += __shfl_xor_sync(0xFFFFFFFFu, v, 16);
    v += __shfl_xor_sync(0xFFFFFFFFu, v, 8);
    v += __shfl_xor_sync(0xFFFFFFFFu, v, 4);
    v += __shfl_xor_sync(0xFFFFFFFFu, v, 2);
    v += __shfl_xor_sync(0xFFFFFFFFu, v, 1);
    return v;
}

__device__ __forceinline__ float dot4(float4 a, float4 b) {
    return a.x * b.x + a.y * b.y + a.z * b.z + a.w * b.w;
}

// 16B register load, L1 non-coherent path, L2 evict_last policy
__device__ __forceinline__ float4 ldg_resident(const float4* p, unsigned long long pol) {
    float4 r;
    asm volatile(
        "ld.global.nc.L2::cache_hint.v4.f32 {%0,%1,%2,%3}, [%4], %5;"
        : "=f"(r.x), "=f"(r.y), "=f"(r.z), "=f"(r.w)
        : "l"(p), "l"(pol));
    return r;
}

// 16B async copy global->shared, bypass L1 (.cg), L2 evict_last policy
__device__ __forceinline__ void cp_async16(unsigned smem_dst, const void* gptr,
                                           unsigned long long pol) {
    asm volatile(
        "cp.async.cg.shared.global.L2::cache_hint [%0], [%1], 16, %2;"
        :: "r"(smem_dst), "l"(gptr), "l"(pol));
}

__global__ void __launch_bounds__(32 * WPB) distmult_kernel(
    const float* __restrict__ A,     // [N_A, 128]
    const float* __restrict__ B,     // [N_B, 128]
    const float* __restrict__ K,     // [128]
    const int*   __restrict__ ep,    // [2, E]
    const int*   __restrict__ hb,    // [E, 4]
    const int*   __restrict__ tb,    // [E, 4]
    float*       __restrict__ out,   // [9E]
    int E)
{
    // staging: [warp][row 0..7][lane] float4 ; rows 0-3 = head-corrupt A rows,
    // rows 4-7 = tail-corrupt B rows. 32 KB per block.
    __shared__ float4 sbuf[WPB][2 * NEG][32];
    __shared__ float  sout[WPB][9];

    int w    = threadIdx.x >> 5;
    int lane = threadIdx.x & 31;
    int e    = blockIdx.x * WPB + w;

    unsigned long long pol;
    asm volatile("createpolicy.fractional.L2::evict_last.b64 %0, 1.0;" : "=l"(pol));

    if (e < E) {
        int h = __ldg(&ep[e]);
        int t = __ldg(&ep[E + e]);
        int4 hbi = __ldg((const int4*)(hb) + e);
        int4 tbi = __ldg((const int4*)(tb) + e);
        int hidx[NEG] = {hbi.x, hbi.y, hbi.z, hbi.w};
        int tidx[NEG] = {tbi.x, tbi.y, tbi.z, tbi.w};

        const float4* A4 = (const float4*)A;
        const float4* B4 = (const float4*)B;

        unsigned sbase = (unsigned)__cvta_generic_to_shared(&sbuf[w][0][lane]);

        // fire all 8 row gathers asynchronously (no registers held in flight)
#pragma unroll
        for (int j = 0; j < NEG; j++) {
            cp_async16(sbase + (unsigned)j * 512u,
                       A4 + (size_t)hidx[j] * (D / 4) + lane, pol);
            cp_async16(sbase + (unsigned)(NEG + j) * 512u,
                       B4 + (size_t)tidx[j] * (D / 4) + lane, pol);
        }
        asm volatile("cp.async.commit_group;");

        // positive-edge rows via regular loads (needed first for ak/bk)
        float4 k4 = __ldg((const float4*)K + lane);
        float4 a  = ldg_resident(A4 + (size_t)h * (D / 4) + lane, pol);
        float4 b  = ldg_resident(B4 + (size_t)t * (D / 4) + lane, pol);

        float4 ak = make_float4(a.x * k4.x, a.y * k4.y, a.z * k4.z, a.w * k4.w);
        float4 bk = make_float4(b.x * k4.x, b.y * k4.y, b.z * k4.z, b.w * k4.w);
        float pos = dot4(ak, b);

        asm volatile("cp.async.wait_group 0;");

        float hs[NEG], ts[NEG];
#pragma unroll
        for (int j = 0; j < NEG; j++) {
            hs[j] = dot4(sbuf[w][j][lane], bk);
            ts[j] = dot4(sbuf[w][NEG + j][lane], ak);
        }

        pos = warp_reduce(pos);
#pragma unroll
        for (int j = 0; j < NEG; j++) {
            hs[j] = warp_reduce(hs[j]);
            ts[j] = warp_reduce(ts[j]);
        }

        // route score j to lane j (all lanes hold all results after xor-reduce)
        float v = pos;
        if (lane == 1) v = hs[0];
        if (lane == 2) v = hs[1];
        if (lane == 3) v = hs[2];
        if (lane == 4) v = hs[3];
        if (lane == 5) v = ts[0];
        if (lane == 6) v = ts[1];
        if (lane == 7) v = ts[2];
        if (lane == 8) v = ts[3];
        if (lane < 9) sout[w][lane] = v;
    }
    __syncthreads();

    // coalesced block-level stores
    int e0 = blockIdx.x * WPB;
    int nb = E - e0; if (nb > WPB) nb = WPB;
    if (nb > 0) {
        int t = threadIdx.x;
        if (t < nb)
            __stcs(&out[e0 + t], sout[t][0]);
        if (t < nb * NEG) {
            int we = t >> 2, j = t & 3;
            __stcs(&out[(size_t)E + (size_t)e0 * NEG + t], sout[we][1 + j]);
            __stcs(&out[(size_t)E * (1 + NEG) + (size_t)e0 * NEG + t], sout[we][5 + j]);
        }
    }
}

extern "C" void kernel_launch(void* const* d_in, const int* in_sizes, int n_in,
                              void* d_out, int out_size) {
    const float* emb_A = (const float*)d_in[0];
    const float* emb_B = (const float*)d_in[1];
    const float* rel_k = (const float*)d_in[2];
    const int*   ep    = (const int*)d_in[3];
    const int*   hb    = (const int*)d_in[4];
    const int*   tb    = (const int*)d_in[5];
    float*       out   = (float*)d_out;

    int E = in_sizes[3] / 2;

    int block = 32 * WPB;
    int grid = (E + WPB - 1) / WPB;
    distmult_kernel<<<grid, block>>>(emb_A, emb_B, rel_k, ep, hb, tb, out, E);
}

// round 5
// speedup vs baseline: 1.2237x; 1.1392x over previous
#include <cuda_runtime.h>

// DistMult scoring. R4: TWO edges per warp, 16 lanes per edge.
// Lane (side, laneh) owns float4 slots {laneh, laneh+16} of each 128-d row.
// Warp reductions run over 16 lanes (xor 8,4,2,1) and serve both edges in
// the same shuffle instructions -> per-edge reduce cost drops 2.5x.
//   pos[e]      = sum_d A[h_e,d] * K[d] * B[t_e,d]
//   head[e*4+j] = sum_d A[hb[e,j],d] * K[d] * B[t_e,d]
//   tail[e*4+j] = sum_d A[h_e,d] * K[d] * B[tb[e,j],d]
// out = [pos (E), head (4E), tail (4E)]

#define D 128
#define NEG 4
#define WPB 4            // warps per block
#define EPB (2 * WPB)    // edges per block

__device__ __forceinline__ float dot4(float4 a, float4 b) {
    return a.x * b.x + a.y * b.y + a.z * b.z + a.w * b.w;
}

__device__ __forceinline__ float4 mul4(float4 a, float4 b) {
    return make_float4(a.x * b.x, a.y * b.y, a.z * b.z, a.w * b.w);
}

// reduce over the 16 lanes of this half-warp (xor masks stay within half)
__device__ __forceinline__ float half_reduce(float v) {
    v += __shfl_xor_sync(0xFFFFFFFFu, v, 8);
    v += __shfl_xor_sync(0xFFFFFFFFu, v, 4);
    v += __shfl_xor_sync(0xFFFFFFFFu, v, 2);
    v += __shfl_xor_sync(0xFFFFFFFFu, v, 1);
    return v;
}

// 16B register load, L1 non-coherent, L2 evict_last
__device__ __forceinline__ float4 ldg_resident(const float4* p, unsigned long long pol) {
    float4 r;
    asm volatile(
        "ld.global.nc.L2::cache_hint.v4.f32 {%0,%1,%2,%3}, [%4], %5;"
        : "=f"(r.x), "=f"(r.y), "=f"(r.z), "=f"(r.w)
        : "l"(p), "l"(pol));
    return r;
}

// 16B async copy global->shared, bypass L1, L2 evict_last
__device__ __forceinline__ void cp_async16(unsigned smem_dst, const void* gptr,
                                           unsigned long long pol) {
    asm volatile(
        "cp.async.cg.shared.global.L2::cache_hint [%0], [%1], 16, %2;"
        :: "r"(smem_dst), "l"(gptr), "l"(pol));
}

__global__ void __launch_bounds__(32 * WPB) distmult_kernel(
    const float* __restrict__ A,     // [N_A, 128]
    const float* __restrict__ B,     // [N_B, 128]
    const float* __restrict__ K,     // [128]
    const int*   __restrict__ ep,    // [2, E]
    const int*   __restrict__ hb,    // [E, 4]
    const int*   __restrict__ tb,    // [E, 4]
    float*       __restrict__ out,   // [9E]
    int E)
{
    // [warp][corrupt row j (0-3 head, 4-7 tail)][slot][lane] -> 8 KB/warp
    __shared__ float4 sbuf[WPB][2 * NEG][2][32];
    __shared__ float  sout[EPB][9];

    int w     = threadIdx.x >> 5;
    int lane  = threadIdx.x & 31;
    int laneh = lane & 15;
    int side  = lane >> 4;
    int gw    = blockIdx.x * WPB + w;
    int e     = 2 * gw + side;

    unsigned long long pol;
    asm volatile("createpolicy.fractional.L2::evict_last.b64 %0, 1.0;" : "=l"(pol));

    if (e < E) {
        int h = __ldg(&ep[e]);
        int t = __ldg(&ep[E + e]);
        int4 hbi = __ldg((const int4*)(hb) + e);
        int4 tbi = __ldg((const int4*)(tb) + e);
        int hidx[NEG] = {hbi.x, hbi.y, hbi.z, hbi.w};
        int tidx[NEG] = {tbi.x, tbi.y, tbi.z, tbi.w};

        const float4* A4 = (const float4*)A;
        const float4* B4 = (const float4*)B;

        // async-stage the 8 corrupt rows for this edge half
        unsigned s0 = (unsigned)__cvta_generic_to_shared(&sbuf[w][0][0][lane]);
#pragma unroll
        for (int j = 0; j < NEG; j++) {
            const float4* hrow = A4 + (size_t)hidx[j] * (D / 4);
            cp_async16(s0 + (unsigned)j * 1024u,        hrow + laneh, pol);
            cp_async16(s0 + (unsigned)j * 1024u + 512u, hrow + 16 + laneh, pol);
        }
#pragma unroll
        for (int j = 0; j < NEG; j++) {
            const float4* trow = B4 + (size_t)tidx[j] * (D / 4);
            cp_async16(s0 + (unsigned)(NEG + j) * 1024u,        trow + laneh, pol);
            cp_async16(s0 + (unsigned)(NEG + j) * 1024u + 512u, trow + 16 + laneh, pol);
        }
        asm volatile("cp.async.commit_group;");

        // positive-edge rows + kernel vector (register loads)
        float4 k0 = __ldg((const float4*)K + laneh);
        float4 k1 = __ldg((const float4*)K + 16 + laneh);
        float4 a0 = ldg_resident(A4 + (size_t)h * (D / 4) + laneh, pol);
        float4 a1 = ldg_resident(A4 + (size_t)h * (D / 4) + 16 + laneh, pol);
        float4 b0 = ldg_resident(B4 + (size_t)t * (D / 4) + laneh, pol);
        float4 b1 = ldg_resident(B4 + (size_t)t * (D / 4) + 16 + laneh, pol);

        float4 ak0 = mul4(a0, k0), ak1 = mul4(a1, k1);
        float4 bk0 = mul4(b0, k0), bk1 = mul4(b1, k1);
        float pos = dot4(ak0, b0) + dot4(ak1, b1);

        asm volatile("cp.async.wait_group 0;");

        float hs[NEG], ts[NEG];
#pragma unroll
        for (int j = 0; j < NEG; j++) {
            hs[j] = dot4(sbuf[w][j][0][lane], bk0) + dot4(sbuf[w][j][1][lane], bk1);
            ts[j] = dot4(sbuf[w][NEG + j][0][lane], ak0) + dot4(sbuf[w][NEG + j][1][lane], ak1);
        }

        pos = half_reduce(pos);
#pragma unroll
        for (int j = 0; j < NEG; j++) {
            hs[j] = half_reduce(hs[j]);
            ts[j] = half_reduce(ts[j]);
        }

        // route score s to lane laneh==s within each half
        float v = pos;
        if (laneh == 1) v = hs[0];
        if (laneh == 2) v = hs[1];
        if (laneh == 3) v = hs[2];
        if (laneh == 4) v = hs[3];
        if (laneh == 5) v = ts[0];
        if (laneh == 6) v = ts[1];
        if (laneh == 7) v = ts[2];
        if (laneh == 8) v = ts[3];
        if (laneh < 9) sout[2 * w + side][laneh] = v;
    }
    __syncthreads();

    // coalesced block-level stores
    int e0 = blockIdx.x * EPB;
    int nb = E - e0; if (nb > EPB) nb = EPB;
    if (nb > 0) {
        int t = threadIdx.x;
        if (t < nb)
            __stcs(&out[e0 + t], sout[t][0]);
        if (t < nb * NEG) {
            int we = t >> 2, j = t & 3;
            __stcs(&out[(size_t)E + (size_t)e0 * NEG + t], sout[we][1 + j]);
            __stcs(&out[(size_t)E * (1 + NEG) + (size_t)e0 * NEG + t], sout[we][5 + j]);
        }
    }
}

extern "C" void kernel_launch(void* const* d_in, const int* in_sizes, int n_in,
                              void* d_out, int out_size) {
    const float* emb_A = (const float*)d_in[0];
    const float* emb_B = (const float*)d_in[1];
    const float* rel_k = (const float*)d_in[2];
    const int*   ep    = (const int*)d_in[3];
    const int*   hb    = (const int*)d_in[4];
    const int*   tb    = (const int*)d_in[5];
    float*       out   = (float*)d_out;

    int E = in_sizes[3] / 2;

    int grid = (E + EPB - 1) / EPB;
    distmult_kernel<<<grid, 32 * WPB>>>(emb_A, emb_B, rel_k, ep, hb, tb, out, E);
}